// round 15
// baseline (speedup 1.0000x reference)
#include <cuda_runtime.h>

// segmentation (2,1,256,256,256) float32, values exactly 0.0f / 1.0f
#define DIM    256
#define NBAT   2
#define TLX    64
#define TLY    32
#define CZ     32
#define NCHUNK (DIM / CZ)   // 8
#define NTHR   256
#define M4     0x0F0F0F0Fu

// pack 4 floats (exactly 0.0f/1.0f) into 4 bytes of a u32 (0x00/0x01)
__device__ __forceinline__ unsigned pack01(float4 v) {
    unsigned q0 = __byte_perm(__float_as_uint(v.x), __float_as_uint(v.y), 0x0073);
    unsigned q1 = __byte_perm(__float_as_uint(v.z), __float_as_uint(v.w), 0x7300);
    return (q0 | q1) & 0x01010101u;
}

// x 5-tap [1,2,3,2,1] on packed bytes; A,B,C consecutive u32; out byte j = window at B byte j
__device__ __forceinline__ unsigned xconv(unsigned A, unsigned B, unsigned C) {
    const unsigned s2 = __byte_perm(A, B, 0x5432);
    const unsigned s3 = __byte_perm(A, B, 0x6543);
    const unsigned s5 = __byte_perm(B, C, 0x4321);
    const unsigned s6 = __byte_perm(B, C, 0x5432);
    return (s2 + s6) + 2u * (s3 + s5) + 3u * B;      // bytes <= 9
}

// per-byte min(v,9); input bytes <= 81
__device__ __forceinline__ unsigned clamp9(unsigned o) {
    const unsigned flag = (o + 0x76767676u) & 0x80808080u;
    const unsigned full = (flag - (flag >> 7)) | flag;
    return (o & ~full) | (0x09090909u & full);
}

// expand flag byte k of m (bit 7) into 0.0f / 1.0f  (R13-proven shift form)
__device__ __forceinline__ float flag2f(unsigned m, int k) {
    return __uint_as_float((unsigned)(((int)(m << (24 - 8 * k))) >> 31) & 0x3F800000u);
}

__global__ __launch_bounds__(NTHR, 4)
void skel_kernel(const float* __restrict__ in, float* __restrict__ out) {
    // 4-slot z-ring of raw halo planes: 36 rows x 72 bytes (cols x0-4..x0+67)
    __shared__ __align__(16) unsigned char raw[4][36 * 72];       // 10.1 KB
    // double-buffered pair of x-conv planes, flat [row*8+vec] uint2
    __shared__ __align__(16) uint2 xcf[2][2][288];                // 9.2 KB

    const int t  = threadIdx.x;              // 0..255
    const int x0 = blockIdx.x * TLX;
    const int y0 = blockIdx.y * TLY;
    const int b  = blockIdx.z / NCHUNK;
    const int zs = (blockIdx.z % NCHUNK) * CZ;

    const size_t planeSz = (size_t)DIM * DIM;
    const float* inb  = in  + (size_t)b * DIM * planeSz;
    float*       outb = out + (size_t)b * DIM * planeSz;

    // ---- halo descriptors: 324 uint2-tasks/plane = 36 rows x 9 ----
    int h1_soff, h1_src; bool h1_okL, h1_okH;
    {
        const int r = t / 9, pv = t - 9 * r;
        const int gy = y0 - 2 + r, gxL = x0 - 4 + 8 * pv;
        const bool gyok = (unsigned)gy < DIM;
        h1_okL = gyok && ((unsigned)gxL < DIM);
        h1_okH = gyok && ((unsigned)(gxL + 4) < DIM);
        h1_src = gy * DIM + gxL;
        h1_soff = 72 * r + 8 * pv;
    }
    const bool h2a = (t < 68);
    int h2_soff = 0, h2_src = 0; bool h2_okL = false, h2_okH = false;
    if (h2a) {
        const int i = t + 256;
        const int r = i / 9, pv = i - 9 * r;
        const int gy = y0 - 2 + r, gxL = x0 - 4 + 8 * pv;
        const bool gyok = (unsigned)gy < DIM;
        h2_okL = gyok && ((unsigned)gxL < DIM);
        h2_okH = gyok && ((unsigned)(gxL + 4) < DIM);
        h2_src = gy * DIM + gxL;
        h2_soff = 72 * r + 8 * pv;
    }

    // ---- x-conv tasks: 288/plane; task t (rows 0..31) + t<32: task t+256 (rows 32..35) ----
    const int  x1_ro = 72 * (t >> 3) + 8 * (t & 7);
    const bool x2a   = (t < 32);
    const int  x2_ro = 72 * (32 + (t >> 3)) + 8 * (t & 7);

    // ---- output mapping: 8 voxels/thread; xc flat index of a_k = t + 8k ----
    const int orow = t >> 3, ov = t & 7;
    const long long obase = (long long)(y0 + orow) * DIM + (x0 + 8 * ov);

    // register ring (uint2): clamped xy-conv bytes (<=9) | center in bit 4
    uint2 r0, r1, r2, r3, r4;
    r0 = r1 = r2 = r3 = r4 = make_uint2(0u, 0u);

    // ---- preload planes gz = zs-2 -> slot 0, zs-1 -> slot 1 ----
    {
        const bool zok = (zs > 0);
        const float* pl0 = inb + (size_t)(zs - 2) * planeSz;
        const float* pl1 = pl0 + planeSz;
        float4 z4 = make_float4(0.f, 0.f, 0.f, 0.f);
        float4 aL = z4, aH = z4, bL = z4, bH = z4;
        if (zok && h1_okL) { aL = *(const float4*)(pl0 + h1_src);
                             bL = *(const float4*)(pl1 + h1_src); }
        if (zok && h1_okH) { aH = *(const float4*)(pl0 + h1_src + 4);
                             bH = *(const float4*)(pl1 + h1_src + 4); }
        *(uint2*)(raw[0] + h1_soff) = make_uint2(pack01(aL), pack01(aH));
        *(uint2*)(raw[1] + h1_soff) = make_uint2(pack01(bL), pack01(bH));
        if (h2a) {
            float4 cL = z4, cH = z4, dL = z4, dH = z4;
            if (zok && h2_okL) { cL = *(const float4*)(pl0 + h2_src);
                                 dL = *(const float4*)(pl1 + h2_src); }
            if (zok && h2_okH) { cH = *(const float4*)(pl0 + h2_src + 4);
                                 dH = *(const float4*)(pl1 + h2_src + 4); }
            *(uint2*)(raw[0] + h2_soff) = make_uint2(pack01(cL), pack01(cH));
            *(uint2*)(raw[1] + h2_soff) = make_uint2(pack01(dL), pack01(dH));
        }
    }
    __syncthreads();

#pragma unroll 2
    for (int it = 0; it < 18; ++it) {
        const int sA = (2 * it) & 3, sB = sA + 1;       // current planes
        const int sC = (sA + 2) & 3, sD = sC + 1;       // commit targets
        uint2* xcA = xcf[it & 1][0];
        uint2* xcB = xcf[it & 1][1];

        // ---- prefetch planes gz = zs+2it, +1 (for next iteration's slots) ----
        float4 z4 = make_float4(0.f, 0.f, 0.f, 0.f);
        float4 aL1 = z4, aH1 = z4, bL1 = z4, bH1 = z4;
        float4 aL2 = z4, aH2 = z4, bL2 = z4, bH2 = z4;
        {
            const int gzA = zs + 2 * it;
            const bool pA = (it < 17) && (gzA < DIM);
            const bool pB = (it < 17) && (gzA + 1 < DIM);
            const float* plA = inb + (size_t)gzA * planeSz;
            const float* plB = plA + planeSz;
            if (pA && h1_okL) aL1 = *(const float4*)(plA + h1_src);
            if (pA && h1_okH) aH1 = *(const float4*)(plA + h1_src + 4);
            if (pB && h1_okL) bL1 = *(const float4*)(plB + h1_src);
            if (pB && h1_okH) bH1 = *(const float4*)(plB + h1_src + 4);
            if (h2a) {
                if (pA && h2_okL) aL2 = *(const float4*)(plA + h2_src);
                if (pA && h2_okH) aH2 = *(const float4*)(plA + h2_src + 4);
                if (pB && h2_okL) bL2 = *(const float4*)(plB + h2_src);
                if (pB && h2_okH) bH2 = *(const float4*)(plB + h2_src + 4);
            }
        }

        // ---- x-conv planes A,B: raw -> xc (center bit embedded at bit 4) ----
        {
            const unsigned char* bA = raw[sA];
            const uint2 q1 = *(const uint2*)(bA + x1_ro);
            const uint2 q2 = *(const uint2*)(bA + x1_ro + 8);
            uint2 o;
            o.x = xconv(q1.x, q1.y, q2.x) | (q1.y << 4);
            o.y = xconv(q1.y, q2.x, q2.y) | (q2.x << 4);
            xcA[t] = o;

            const unsigned char* bB = raw[sB];
            const uint2 s1 = *(const uint2*)(bB + x1_ro);
            const uint2 s2 = *(const uint2*)(bB + x1_ro + 8);
            uint2 p;
            p.x = xconv(s1.x, s1.y, s2.x) | (s1.y << 4);
            p.y = xconv(s1.y, s2.x, s2.y) | (s2.x << 4);
            xcB[t] = p;

            if (x2a) {
                const uint2 u1 = *(const uint2*)(bA + x2_ro);
                const uint2 u2 = *(const uint2*)(bA + x2_ro + 8);
                uint2 oo;
                oo.x = xconv(u1.x, u1.y, u2.x) | (u1.y << 4);
                oo.y = xconv(u1.y, u2.x, u2.y) | (u2.x << 4);
                xcA[t + 256] = oo;
                const uint2 w1 = *(const uint2*)(bB + x2_ro);
                const uint2 w2 = *(const uint2*)(bB + x2_ro + 8);
                uint2 pp;
                pp.x = xconv(w1.x, w1.y, w2.x) | (w1.y << 4);
                pp.y = xconv(w1.y, w2.x, w2.y) | (w2.x << 4);
                xcB[t + 256] = pp;
            }
        }

        // ---- commit prefetched planes into slots sC, sD ----
        *(uint2*)(raw[sC] + h1_soff) = make_uint2(pack01(aL1), pack01(aH1));
        *(uint2*)(raw[sD] + h1_soff) = make_uint2(pack01(bL1), pack01(bH1));
        if (h2a) {
            *(uint2*)(raw[sC] + h2_soff) = make_uint2(pack01(aL2), pack01(aH2));
            *(uint2*)(raw[sD] + h2_soff) = make_uint2(pack01(bL2), pack01(bH2));
        }
        __syncthreads();   // xc ready AND raw[sC/sD] ready (single barrier)

        // ---- plane A: y-conv + clamp + center, ring push, emit zo = zs+2it-4 ----
        {
            const uint2 a0 = xcA[t];
            const uint2 a1 = xcA[t + 8];
            const uint2 a2 = xcA[t + 16];
            const uint2 a3 = xcA[t + 24];
            const uint2 a4 = xcA[t + 32];
            uint2 p;
            p.x = clamp9(((a0.x & M4) + (a4.x & M4)) + 2u * ((a1.x & M4) + (a3.x & M4))
                         + 3u * (a2.x & M4)) | (a2.x & 0x10101010u);
            p.y = clamp9(((a0.y & M4) + (a4.y & M4)) + 2u * ((a1.y & M4) + (a3.y & M4))
                         + 3u * (a2.y & M4)) | (a2.y & 0x10101010u);
            r0 = r1; r1 = r2; r2 = r3; r3 = r4; r4 = p;
        }
        if (it >= 2) {
            const unsigned dx = ((r0.x & M4) + (r4.x & M4)) + 2u * ((r1.x & M4) + (r3.x & M4)) + 3u * (r2.x & M4);
            const unsigned dy = ((r0.y & M4) + (r4.y & M4)) + 2u * ((r1.y & M4) + (r3.y & M4)) + 3u * (r2.y & M4);
            const unsigned mx = (dx + 0x77777777u) & ~(r2.x << 3) & 0x80808080u;
            const unsigned my = (dy + 0x77777777u) & ~(r2.y << 3) & 0x80808080u;
            float4 o1 = make_float4(flag2f(mx, 0), flag2f(mx, 1), flag2f(mx, 2), flag2f(mx, 3));
            float4 o2 = make_float4(flag2f(my, 0), flag2f(my, 1), flag2f(my, 2), flag2f(my, 3));
            float* op = outb + (size_t)(zs + 2 * it - 4) * planeSz + obase;
            __stcs((float4*)op, o1);
            __stcs((float4*)(op + 4), o2);
        }

        // ---- plane B ----
        {
            const uint2 a0 = xcB[t];
            const uint2 a1 = xcB[t + 8];
            const uint2 a2 = xcB[t + 16];
            const uint2 a3 = xcB[t + 24];
            const uint2 a4 = xcB[t + 32];
            uint2 p;
            p.x = clamp9(((a0.x & M4) + (a4.x & M4)) + 2u * ((a1.x & M4) + (a3.x & M4))
                         + 3u * (a2.x & M4)) | (a2.x & 0x10101010u);
            p.y = clamp9(((a0.y & M4) + (a4.y & M4)) + 2u * ((a1.y & M4) + (a3.y & M4))
                         + 3u * (a2.y & M4)) | (a2.y & 0x10101010u);
            r0 = r1; r1 = r2; r2 = r3; r3 = r4; r4 = p;
        }
        if (it >= 2) {
            const unsigned dx = ((r0.x & M4) + (r4.x & M4)) + 2u * ((r1.x & M4) + (r3.x & M4)) + 3u * (r2.x & M4);
            const unsigned dy = ((r0.y & M4) + (r4.y & M4)) + 2u * ((r1.y & M4) + (r3.y & M4)) + 3u * (r2.y & M4);
            const unsigned mx = (dx + 0x77777777u) & ~(r2.x << 3) & 0x80808080u;
            const unsigned my = (dy + 0x77777777u) & ~(r2.y << 3) & 0x80808080u;
            float4 o1 = make_float4(flag2f(mx, 0), flag2f(mx, 1), flag2f(mx, 2), flag2f(mx, 3));
            float4 o2 = make_float4(flag2f(my, 0), flag2f(my, 1), flag2f(my, 2), flag2f(my, 3));
            float* op = outb + (size_t)(zs + 2 * it - 3) * planeSz + obase;
            __stcs((float4*)op, o1);
            __stcs((float4*)(op + 4), o2);
        }
    }
}

extern "C" void kernel_launch(void* const* d_in, const int* in_sizes, int n_in,
                              void* d_out, int out_size) {
    (void)in_sizes; (void)n_in; (void)out_size;
    const float* seg = (const float*)d_in[0];
    float* out = (float*)d_out;

    dim3 block(NTHR, 1, 1);
    dim3 grid(DIM / TLX, DIM / TLY, NBAT * NCHUNK);   // 4 x 8 x 16 = 512 blocks
    skel_kernel<<<grid, block>>>(seg, out);
}